// round 5
// baseline (speedup 1.0000x reference)
#include <cuda_runtime.h>
#include <cuda_bf16.h>
#include <math.h>

#define T_TOK 4096
#define DIM   1024
#define NEXP  8
#define WEXP  1024
#define EW    8192
#define PMAX  9216
#define NRT   72

#define BM 128
#define BN 128
#define BK 16

__device__ float g_a[(size_t)PMAX * WEXP];
__device__ float g_part[(size_t)2 * T_TOK * DIM];
__device__ int   g_pairid[PMAX];
__device__ float g_pairwt[PMAX];
__device__ int   g_sel[T_TOK * 2];
__device__ float g_wt[T_TOK * 2];
__device__ int   g_cnt[NEXP];
__device__ int   g_cursor[NEXP];
__device__ int   g_tile_e[NRT];

__global__ void k_reset() {
    if (threadIdx.x < NEXP) g_cnt[threadIdx.x] = 0;
}

__global__ __launch_bounds__(256) void k_router(const float* __restrict__ x,
                                                const float* __restrict__ rw) {
    __shared__ float s_rw[NEXP * DIM];
    for (int i = threadIdx.x; i < NEXP * DIM; i += blockDim.x) s_rw[i] = rw[i];
    __syncthreads();

    const int warp = threadIdx.x >> 5;
    const int lane = threadIdx.x & 31;
    const int t = blockIdx.x * 8 + warp;
    if (t >= T_TOK) return;

    const float* xr = x + (size_t)t * DIM;
    float acc[NEXP];
#pragma unroll
    for (int e = 0; e < NEXP; e++) acc[e] = 0.f;

    for (int d = lane; d < DIM; d += 32) {
        float xv = xr[d];
#pragma unroll
        for (int e = 0; e < NEXP; e++) acc[e] += xv * s_rw[e * DIM + d];
    }
#pragma unroll
    for (int e = 0; e < NEXP; e++)
#pragma unroll
        for (int off = 16; off; off >>= 1)
            acc[e] += __shfl_xor_sync(0xffffffffu, acc[e], off);

    if (lane == 0) {
        float best = -1e30f, sec = -1e30f;
        int bi = 0, si = 0;
#pragma unroll
        for (int e = 0; e < NEXP; e++) {
            float p = 1.f / (1.f + expf(-acc[e]));
            if (p > best) { sec = best; si = bi; best = p; bi = e; }
            else if (p > sec) { sec = p; si = e; }
        }
        float s = best + sec + 1e-20f;
        g_sel[t * 2 + 0] = bi;
        g_sel[t * 2 + 1] = si;
        g_wt[t * 2 + 0] = best / s;
        g_wt[t * 2 + 1] = sec / s;
        atomicAdd(&g_cnt[bi], 1);
        atomicAdd(&g_cnt[si], 1);
    }
}

__global__ void k_setup() {
    if (threadIdx.x == 0) {
        int offs[NEXP + 1];
        offs[0] = 0;
        for (int e = 0; e < NEXP; e++) {
            g_cursor[e] = offs[e];
            offs[e + 1] = offs[e] + ((g_cnt[e] + 127) & ~127);
        }
        for (int r = 0; r < NRT; r++) {
            int rb = r * 128;
            int ee = -1;
            for (int e = 0; e < NEXP; e++)
                if (rb >= offs[e] && rb < offs[e + 1]) ee = e;
            g_tile_e[r] = ee;
        }
    }
    for (int i = threadIdx.x; i < PMAX; i += blockDim.x) {
        g_pairid[i] = -1;
        g_pairwt[i] = 0.f;
    }
}

__global__ void k_scatter() {
    int t = blockIdx.x * blockDim.x + threadIdx.x;
    if (t >= T_TOK) return;
#pragma unroll
    for (int k = 0; k < 2; k++) {
        int e = g_sel[t * 2 + k];
        int pos = atomicAdd(&g_cursor[e], 1);
        g_pairid[pos] = t * 2 + k;
        g_pairwt[pos] = g_wt[t * 2 + k];
    }
}

__global__ __launch_bounds__(256) void k_gemm_up(const float* __restrict__ x,
                                                 const float* __restrict__ w1) {
    const int r = blockIdx.y;
    const int e = g_tile_e[r];
    if (e < 0) return;
    const int cb = blockIdx.x;
    const int base = r * BM;

    __shared__ float As[2][BK][BM];
    __shared__ float Bs[2][BK][BN];

    const int tid = threadIdx.x;
    const int ty = tid >> 4, tx = tid & 15;

    const int arow = tid >> 2;
    const int akk  = (tid & 3) * 4;
    const int pid0 = g_pairid[base + arow];
    const int pid1 = g_pairid[base + arow + 64];
    const float* ax0 = (pid0 >= 0) ? x + (size_t)(pid0 >> 1) * DIM : nullptr;
    const float* ax1 = (pid1 >= 0) ? x + (size_t)(pid1 >> 1) * DIM : nullptr;

    const int bk   = tid >> 5;
    const int bcol = (tid & 31) * 4;
    const float* bbase = w1 + (size_t)e * WEXP + (size_t)cb * BN + bcol;

    const float4 Z = make_float4(0.f, 0.f, 0.f, 0.f);
    float acc[8][8];
#pragma unroll
    for (int i = 0; i < 8; i++)
#pragma unroll
        for (int j = 0; j < 8; j++) acc[i][j] = 0.f;

    {
        float4 a0 = ax0 ? *(const float4*)(ax0 + akk) : Z;
        float4 a1 = ax1 ? *(const float4*)(ax1 + akk) : Z;
        float4 b0 = *(const float4*)(bbase + (size_t)bk * EW);
        float4 b1 = *(const float4*)(bbase + (size_t)(bk + 8) * EW);
        As[0][akk + 0][arow] = a0.x; As[0][akk + 1][arow] = a0.y;
        As[0][akk + 2][arow] = a0.z; As[0][akk + 3][arow] = a0.w;
        As[0][akk + 0][arow + 64] = a1.x; As[0][akk + 1][arow + 64] = a1.y;
        As[0][akk + 2][arow + 64] = a1.z; As[0][akk + 3][arow + 64] = a1.w;
        *(float4*)&Bs[0][bk][bcol] = b0;
        *(float4*)&Bs[0][bk + 8][bcol] = b1;
    }
    __syncthreads();

    const int KT = DIM / BK;
    for (int kt = 0; kt < KT; ++kt) {
        const int cur = kt & 1;
        float4 na0 = Z, na1 = Z, nb0 = Z, nb1 = Z;
        if (kt < KT - 1) {
            const int k0 = (kt + 1) * BK;
            na0 = ax0 ? *(const float4*)(ax0 + k0 + akk) : Z;
            na1 = ax1 ? *(const float4*)(ax1 + k0 + akk) : Z;
            nb0 = *(const float4*)(bbase + (size_t)(k0 + bk) * EW);
            nb1 = *(const float4*)(bbase + (size_t)(k0 + bk + 8) * EW);
        }
#pragma unroll
        for (int k = 0; k < BK; k++) {
            float4 ra0 = *(const float4*)&As[cur][k][ty * 8];
            float4 ra1 = *(const float4*)&As[cur][k][ty * 8 + 4];
            float4 rb0 = *(const float4*)&Bs[cur][k][tx * 8];
            float4 rb1 = *(const float4*)&Bs[cur][k][tx * 8 + 4];
            float aa[8] = {ra0.x, ra0.y, ra0.z, ra0.w, ra1.x, ra1.y, ra1.z, ra1.w};
            float bb[8] = {rb0.x, rb0.y, rb0.z, rb0.w, rb1.x, rb1.y, rb1.z, rb1.w};
#pragma unroll
            for (int i = 0; i < 8; i++)
#pragma unroll
                for (int j = 0; j < 8; j++) acc[i][j] += aa[i] * bb[j];
        }
        if (kt < KT - 1) {
            const int nxt = cur ^ 1;
            As[nxt][akk + 0][arow] = na0.x; As[nxt][akk + 1][arow] = na0.y;
            As[nxt][akk + 2][arow] = na0.z; As[nxt][akk + 3][arow] = na0.w;
            As[nxt][akk + 0][arow + 64] = na1.x; As[nxt][akk + 1][arow + 64] = na1.y;
            As[nxt][akk + 2][arow + 64] = na1.z; As[nxt][akk + 3][arow + 64] = na1.w;
            *(float4*)&Bs[nxt][bk][bcol] = nb0;
            *(float4*)&Bs[nxt][bk + 8][bcol] = nb1;
        }
        __syncthreads();
    }

#pragma unroll
    for (int i = 0; i < 8; i++) {
        const int row = base + ty * 8 + i;
        float* dst = g_a + (size_t)row * WEXP + (size_t)cb * BN + tx * 8;
        float o[8];
#pragma unroll
        for (int j = 0; j < 8; j++) {
            float v = acc[i][j];
            v = v > 0.f ? v : 0.f;
            o[j] = v * v;
        }
        *(float4*)dst       = make_float4(o[0], o[1], o[2], o[3]);
        *(float4*)(dst + 4) = make_float4(o[4], o[5], o[6], o[7]);
    }
}

__global__ __launch_bounds__(256) void k_gemm_down(const float* __restrict__ w2) {
    const int r = blockIdx.y;
    const int e = g_tile_e[r];
    if (e < 0) return;
    const int cb = blockIdx.x;
    const int base = r * BM;

    __shared__ float As[2][BK][BM];
    __shared__ float Bs[2][BK][BN];

    const int tid = threadIdx.x;
    const int ty = tid >> 4, tx = tid & 15;

    const int arow = tid >> 2;
    const int akk  = (tid & 3) * 4;
    const float* ax0 = g_a + (size_t)(base + arow) * WEXP;
    const float* ax1 = g_a + (size_t)(base + arow + 64) * WEXP;

    const int bk   = tid >> 5;
    const int bcol = (tid & 31) * 4;
    const float* bbase = w2 + ((size_t)e * WEXP) * DIM + (size_t)cb * BN + bcol;

    float acc[8][8];
#pragma unroll
    for (int i = 0; i < 8; i++)
#pragma unroll
        for (int j = 0; j < 8; j++) acc[i][j] = 0.f;

    {
        float4 a0 = *(const float4*)(ax0 + akk);
        float4 a1 = *(const float4*)(ax1 + akk);
        float4 b0 = *(const float4*)(bbase + (size_t)bk * DIM);
        float4 b1 = *(const float4*)(bbase + (size_t)(bk + 8) * DIM);
        As[0][akk + 0][arow] = a0.x; As[0][akk + 1][arow] = a0.y;
        As[0][akk + 2][arow] = a0.z; As[0][akk + 3][arow] = a0.w;
        As[0][akk + 0][arow + 64] = a1.x; As[0][akk + 1][arow + 64] = a1.y;
        As[0][akk + 2][arow + 64] = a1.z; As[0][akk + 3][arow + 64] = a1.w;
        *(float4*)&Bs[0][bk][bcol] = b0;
        *(float4*)&Bs[0][bk + 8][bcol] = b1;
    }
    __syncthreads();

    const int KT = WEXP / BK;
    for (int kt = 0; kt < KT; ++kt) {
        const int cur = kt & 1;
        float4 na0, na1, nb0, nb1;
        if (kt < KT - 1) {
            const int k0 = (kt + 1) * BK;
            na0 = *(const float4*)(ax0 + k0 + akk);
            na1 = *(const float4*)(ax1 + k0 + akk);
            nb0 = *(const float4*)(bbase + (size_t)(k0 + bk) * DIM);
            nb1 = *(const float4*)(bbase + (size_t)(k0 + bk + 8) * DIM);
        }
#pragma unroll
        for (int k = 0; k < BK; k++) {
            float4 ra0 = *(const float4*)&As[cur][k][ty * 8];
            float4 ra1 = *(const float4*)&As[cur][k][ty * 8 + 4];
            float4 rb0 = *(const float4*)&Bs[cur][k][tx * 8];
            float4 rb1 = *(const float4*)&Bs[cur][k][tx * 8 + 4];
            float aa[8] = {ra0.x, ra0.y, ra0.z, ra0.w, ra1.x, ra1.y, ra1.z, ra1.w};
            float bb[8] = {rb0.x, rb0.y, rb0.z, rb0.w, rb1.x, rb1.y, rb1.z, rb1.w};
#pragma unroll
            for (int i = 0; i < 8; i++)
#pragma unroll
                for (int j = 0; j < 8; j++) acc[i][j] += aa[i] * bb[j];
        }
        if (kt < KT - 1) {
            const int nxt = cur ^ 1;
            As[nxt][akk + 0][arow] = na0.x; As[nxt][akk + 1][arow] = na0.y;
            As[nxt][akk + 2][arow] = na0.z; As[nxt][akk + 3][arow] = na0.w;
            As[nxt][akk + 0][arow + 64] = na1.x; As[nxt][akk + 1][arow + 64] = na1.y;
            As[nxt][akk + 2][arow + 64] = na1.z; As[nxt][akk + 3][arow + 64] = na1.w;
            *(float4*)&Bs[nxt][bk][bcol] = nb0;
            *(float4*)&Bs[nxt][bk + 8][bcol] = nb1;
        }
        __syncthreads();
    }

#pragma unroll
    for (int i = 0; i < 8; i++) {
        const int row = base + ty * 8 + i;
        const int pid = g_pairid[row];
        if (pid < 0) continue;
        const float wtv = g_pairwt[row];
        float* dst = g_part + (size_t)(pid & 1) * ((size_t)T_TOK * DIM)
                            + (size_t)(pid >> 1) * DIM + (size_t)cb * BN + tx * 8;
        *(float4*)dst = make_float4(wtv * acc[i][0], wtv * acc[i][1],
                                    wtv * acc[i][2], wtv * acc[i][3]);
        *(float4*)(dst + 4) = make_float4(wtv * acc[i][4], wtv * acc[i][5],
                                          wtv * acc[i][6], wtv * acc[i][7]);
    }
}

__global__ void k_combine(float* __restrict__ out) {
    const int i = blockIdx.x * blockDim.x + threadIdx.x;
    const float4* p0 = (const float4*)g_part;
    const float4* p1 = (const float4*)(g_part + (size_t)T_TOK * DIM);
    float4 a = p0[i], b = p1[i];
    ((float4*)out)[i] = make_float4(a.x + b.x, a.y + b.y, a.z + b.z, a.w + b.w);
}

extern "C" void kernel_launch(void* const* d_in, const int* in_sizes, int n_in,
                              void* d_out, int out_size) {
    const float* x   = (const float*)d_in[0];   // [B*S, D] = [4096, 1024]
    const float* rw  = (const float*)d_in[1];   // [8, 1024]
    const float* w1  = (const float*)d_in[2];   // [1024, 8192]
    const float* w2  = (const float*)d_in[3];   // [8192, 1024]
    float* out = (float*)d_out;

    k_reset<<<1, 32>>>();
    k_router<<<T_TOK / 8, 256>>>(x, rw);
    k_setup<<<1, 256>>>();
    k_scatter<<<T_TOK / 256, 256>>>();
    k_gemm_up<<<dim3(WEXP / BN, NRT), 256>>>(x, w1);
    k_gemm_down<<<dim3(DIM / BN, NRT), 256>>>(w2);
    k_combine<<<(T_TOK * DIM / 4) / 256, 256>>>(out);
}